// round 2
// baseline (speedup 1.0000x reference)
#include <cuda_runtime.h>

// BeliefMatchingLoss: pred [8,19,512,512] f32, target [8,512,512] int32 -> scalar f32
// (JAX x64 is disabled, so the declared int64 target is actually int32.)
//
// loss_pix = 0.01*( lnG(a0) - (a0-19)*psi(a0) + sum_c g(a_c) ) + psi(a0) - psi(a_ans)
// with g(x) = (x-1)*psi(x) - lnG(x),  a_c = exp(pred_c),  a0 = sum_c a_c.
// Output = sum(loss_pix * valid) / sum(valid),  valid = (target != 255).

#define HW_   (512 * 512)
#define NC_   19
#define NPIX_ (8 * HW_)

__device__ double             g_sum;
__device__ unsigned long long g_cnt;

__global__ void bml_init() {
    g_sum = 0.0;
    g_cnt = 0ull;
}

// Combined digamma + lgamma via shift-by-4 + asymptotic series.
// P(x) = x(x+1)(x+2)(x+3):  Sum 1/(x+k) = P'(x)/P(x),  Sum ln(x+k) = ln P(x).
__device__ __forceinline__ void psi_lg(float x, float& psi, float& lg) {
    float z  = x + 4.0f;
    float a  = x * (x + 3.0f);          // x^2 + 3x
    float P  = a * (a + 2.0f);          // x(x+1)(x+2)(x+3)
    float Pp = fmaf(fmaf(fmaf(4.0f, x, 18.0f), x, 22.0f), x, 6.0f);  // P'(x)
    float S   = __fdividef(Pp, P);      // sum 1/(x+k)
    float lnP = __logf(P);              // sum ln(x+k)
    float lnz = __logf(z);
    float rz  = __fdividef(1.0f, z);
    float rz2 = rz * rz;

    // psi(z) = ln z - 1/(2z) - 1/(12 z^2) + 1/(120 z^4) - 1/(252 z^6)
    float pi  = fmaf(rz2, -(1.0f / 252.0f), 1.0f / 120.0f);
    float pi2 = fmaf(-rz2, pi, 1.0f / 12.0f);
    float psi_z = lnz - fmaf(0.5f, rz, rz2 * pi2);

    // lnG(z) = (z-0.5) ln z - z + 0.5 ln(2pi) + 1/(12z) - 1/(360 z^3) + 1/(1260 z^5)
    float li  = fmaf(rz2, -(1.0f / 1260.0f), 1.0f / 360.0f);
    float li2 = fmaf(-rz2, li, 1.0f / 12.0f);
    float lg_z = fmaf(z - 0.5f, lnz, -z) + 0.91893853320467274f + rz * li2;

    psi = psi_z - S;
    lg  = lg_z - lnP;
}

__global__ __launch_bounds__(256) void bml_main(const float* __restrict__ pred,
                                                const int* __restrict__ tgt) {
    int pix = blockIdx.x * blockDim.x + threadIdx.x;

    float loss  = 0.0f;
    int   valid = 0;

    if (pix < NPIX_) {
        int b  = pix >> 18;           // / HW_
        int hw = pix & (HW_ - 1);
        const float* pp = pred + (size_t)b * NC_ * HW_ + hw;

        int  tv  = tgt[pix];
        bool ign = (tv == 255);
        int  ta  = ign ? 0 : tv;

        float a0 = 0.0f, sum_g = 0.0f, psi_ans = 0.0f;

#pragma unroll
        for (int c = 0; c < NC_; ++c) {
            float p = pp[(size_t)c * HW_];
            float x = __expf(p);
            float psi, lg;
            psi_lg(x, psi, lg);
            a0    += x;
            sum_g += fmaf(x - 1.0f, psi, -lg);   // g(x)
            if (c == ta) psi_ans = psi;
        }

        float psi0, lg0;
        psi_lg(a0, psi0, lg0);

        float kl = fmaf(-(a0 - (float)NC_), psi0, lg0) + sum_g;
        float l  = fmaf(0.01f, kl, psi0 - psi_ans);

        loss  = ign ? 0.0f : l;
        valid = ign ? 0 : 1;
    }

    // warp reduction
#pragma unroll
    for (int o = 16; o; o >>= 1) {
        loss  += __shfl_down_sync(0xffffffffu, loss, o);
        valid += __shfl_down_sync(0xffffffffu, valid, o);
    }

    __shared__ float s_l[8];
    __shared__ int   s_v[8];
    int wid = threadIdx.x >> 5;
    int lid = threadIdx.x & 31;
    if (lid == 0) { s_l[wid] = loss; s_v[wid] = valid; }
    __syncthreads();

    if (threadIdx.x == 0) {
        float L = 0.0f;
        int   V = 0;
#pragma unroll
        for (int w = 0; w < 8; ++w) { L += s_l[w]; V += s_v[w]; }
        atomicAdd(&g_sum, (double)L);
        atomicAdd(&g_cnt, (unsigned long long)V);
    }
}

__global__ void bml_fin(float* out) {
    out[0] = (float)(g_sum / (double)g_cnt);
}

extern "C" void kernel_launch(void* const* d_in, const int* in_sizes, int n_in,
                              void* d_out, int out_size) {
    const float* pred = (const float*)d_in[0];
    const int*   tgt  = (const int*)d_in[1];
    float*       out  = (float*)d_out;

    bml_init<<<1, 1>>>();
    bml_main<<<(NPIX_ + 255) / 256, 256>>>(pred, tgt);
    bml_fin<<<1, 1>>>(out);
}

// round 3
// speedup vs baseline: 1.0684x; 1.0684x over previous
#include <cuda_runtime.h>

// BeliefMatchingLoss: pred [8,19,512,512] f32, target [8,512,512] int32 -> scalar f32
//
// loss_pix = 0.01*( lnG(a0) - (a0-19)*psi(a0) + sum_c g(a_c) ) + psi(a0) - psi(a_ans)
// g(x) = (x-1)psi(x) - lnG(x), expanded with shift-2 (z=x+2, P=x(x+1)):
//   g = lnP - 2.5*lnz - (x-1)(c(z)+S) - t(z) + z - C,  S = P'/P, C = 0.5*ln(2pi)
// Sum over classes; logs batched (pairwise P-products, grouped z-products),
// reciprocals batched pairwise. All polynomial math packed 2-pixels/thread
// via fma.rn.f32x2 (sm_103a packed fp32 pipe).

typedef unsigned long long u64;

#define HW_   (512 * 512)
#define NC_   19
#define NPIX_ (8 * HW_)
#define NTHR_ (NPIX_ / 2)

#define LN2F        0.6931471805599453f
#define LOG2EF      1.4426950408889634f
#define HALF_LN_2PI 0.91893853320467274f

__device__ double             g_sum;
__device__ unsigned long long g_cnt;

__global__ void bml_init() { g_sum = 0.0; g_cnt = 0ull; }

// ---- packed f32x2 helpers (values carried as u64 = {lo,hi} fp32 pair) ----
__device__ __forceinline__ u64 pk2(float a, float b) {
    u64 r; asm("mov.b64 %0,{%1,%2};" : "=l"(r) : "f"(a), "f"(b)); return r;
}
__device__ __forceinline__ void upk2(u64 v, float& a, float& b) {
    asm("mov.b64 {%0,%1},%2;" : "=f"(a), "=f"(b) : "l"(v));
}
__device__ __forceinline__ u64 f2fma(u64 a, u64 b, u64 c) {
    u64 d; asm("fma.rn.f32x2 %0,%1,%2,%3;" : "=l"(d) : "l"(a), "l"(b), "l"(c)); return d;
}
__device__ __forceinline__ u64 f2mul(u64 a, u64 b) {
    u64 d; asm("mul.rn.f32x2 %0,%1,%2;" : "=l"(d) : "l"(a), "l"(b)); return d;
}
__device__ __forceinline__ u64 f2add(u64 a, u64 b) {
    u64 d; asm("add.rn.f32x2 %0,%1,%2;" : "=l"(d) : "l"(a), "l"(b)); return d;
}
__device__ __forceinline__ float ex2f(float x) { float r; asm("ex2.approx.f32 %0,%1;" : "=f"(r) : "f"(x)); return r; }
__device__ __forceinline__ float lg2f_(float x){ float r; asm("lg2.approx.f32 %0,%1;" : "=f"(r) : "f"(x)); return r; }
__device__ __forceinline__ float rcpf_(float x){ float r; asm("rcp.approx.f32 %0,%1;" : "=f"(r) : "f"(x)); return r; }
__device__ __forceinline__ u64 ex2_2(u64 v) { float a, b; upk2(v, a, b); return pk2(ex2f(a), ex2f(b)); }
__device__ __forceinline__ u64 rcp_2(u64 v) { float a, b; upk2(v, a, b); return pk2(rcpf_(a), rcpf_(b)); }

// scalar digamma+lgamma, shift-2 (used once per pixel, on a0 which is >> 1)
__device__ __forceinline__ void psi_lg_s(float x, float& psi, float& lg) {
    float z   = x + 2.0f;
    float P   = fmaf(x, x, x);
    float Pp  = fmaf(2.0f, x, 1.0f);
    float r   = rcpf_(P * z);
    float S   = Pp * (z * r);
    float rz  = P * r;
    float rz2 = rz * rz;
    float lnz = lg2f_(z) * LN2F;
    float lnP = lg2f_(P) * LN2F;
    float c = fmaf(rz, 0.5f, rz2 * fmaf(rz2, -1.0f / 120.0f, 1.0f / 12.0f));
    float t = rz * fmaf(rz2, -1.0f / 360.0f, 1.0f / 12.0f);
    psi = lnz - c - S;
    lg  = fmaf(z - 0.5f, lnz, -z) + HALF_LN_2PI + t - lnP;
}

struct ClsA { u64 x, z, P, Pp, Q; };

__global__ __launch_bounds__(256) void bml_main(const float* __restrict__ pred,
                                                const int* __restrict__ tgt) {
    int tix = blockIdx.x * 256 + threadIdx.x;
    int pix = tix * 2;                 // this thread handles pixels pix, pix+1
    int b   = pix >> 18;               // / HW_
    int hw  = pix & (HW_ - 1);
    const float* pp = pred + (size_t)b * NC_ * HW_ + hw;

    int  t0  = tgt[pix];
    int  t1  = tgt[pix + 1];
    bool ig0 = (t0 == 255), ig1 = (t1 == 255);
    int  ta0 = ig0 ? 0 : t0;
    int  ta1 = ig1 ? 0 : t1;

    const u64 KL2E  = pk2(LOG2EF, LOG2EF);
    const u64 K1    = pk2(1.0f, 1.0f);
    const u64 K2    = pk2(2.0f, 2.0f);
    const u64 KH    = pk2(0.5f, 0.5f);
    const u64 Km1   = pk2(-1.0f, -1.0f);
    const u64 K12   = pk2(1.0f / 12.0f, 1.0f / 12.0f);
    const u64 Km120 = pk2(-1.0f / 120.0f, -1.0f / 120.0f);
    const u64 Km360 = pk2(-1.0f / 360.0f, -1.0f / 360.0f);
    const u64 Z64   = pk2(0.0f, 0.0f);

    u64 accW = Z64, accT = Z64, a0v = Z64;
    u64 zp0 = K1, zp1 = K1, zp2 = K1;      // grouped z-products (<=8 per group)
    float lgp_lo = 0.0f, lgp_hi = 0.0f;    // sum of lg2(P) per pixel
    float cs_a0 = 0.0f, cs_a1 = 0.0f, z_a0 = 1.0f, z_a1 = 1.0f;

#define STAGE1(s, c) do {                                                   \
        u64 pv = *reinterpret_cast<const u64*>(pp + (size_t)(c) * HW_);     \
        (s).x  = ex2_2(f2mul(pv, KL2E));                                    \
        (s).z  = f2add((s).x, K2);                                          \
        (s).P  = f2fma((s).x, (s).x, (s).x);                                \
        (s).Pp = f2fma((s).x, K2, K1);                                      \
        (s).Q  = f2mul((s).P, (s).z);                                       \
    } while (0)

#define STAGE2(s, r, c, zpg) do {                                           \
        u64 rz  = f2mul((s).P, (r));                                        \
        u64 S   = f2mul((s).Pp, f2mul((s).z, (r)));                         \
        u64 rz2 = f2mul(rz, rz);                                            \
        u64 v_  = f2mul(rz2, f2fma(rz2, Km120, K12));                       \
        u64 cs  = f2add(f2fma(rz, KH, v_), S);                              \
        u64 tt  = f2mul(rz, f2fma(rz2, Km360, K12));                        \
        u64 xm1 = f2add((s).x, Km1);                                        \
        accW = f2fma(xm1, cs, accW);                                        \
        accT = f2add(accT, tt);                                             \
        a0v  = f2add(a0v, (s).x);                                           \
        (zpg) = f2mul((zpg), (s).z);                                        \
        float cslo, cshi, zlo, zhi;                                         \
        upk2(cs, cslo, cshi); upk2((s).z, zlo, zhi);                        \
        if ((c) == ta0) { cs_a0 = cslo; z_a0 = zlo; }                       \
        if ((c) == ta1) { cs_a1 = cshi; z_a1 = zhi; }                       \
    } while (0)

#pragma unroll
    for (int k = 0; k < 9; ++k) {
        const int c0 = 2 * k, c1 = 2 * k + 1;
        ClsA s0, s1;
        STAGE1(s0, c0);
        STAGE1(s1, c1);
        // paired reciprocal: one RCP per pixel covers both classes
        u64 rr = rcp_2(f2mul(s0.Q, s1.Q));
        u64 r0 = f2mul(rr, s1.Q);
        u64 r1 = f2mul(rr, s0.Q);
        // paired log: ln(P0*P1)
        u64 PPm = f2mul(s0.P, s1.P);
        float ppl, pph; upk2(PPm, ppl, pph);
        lgp_lo += lg2f_(ppl);
        lgp_hi += lg2f_(pph);
        if (c0 < 8)       { STAGE2(s0, r0, c0, zp0); STAGE2(s1, r1, c1, zp0); }
        else if (c0 < 16) { STAGE2(s0, r0, c0, zp1); STAGE2(s1, r1, c1, zp1); }
        else              { STAGE2(s0, r0, c0, zp2); STAGE2(s1, r1, c1, zp2); }
    }
    { // tail class 18 (unpaired)
        ClsA s;
        STAGE1(s, 18);
        u64 r = rcp_2(s.Q);
        float ppl, pph; upk2(s.P, ppl, pph);
        lgp_lo += lg2f_(ppl);
        lgp_hi += lg2f_(pph);
        STAGE2(s, r, 18, zp2);
    }
#undef STAGE1
#undef STAGE2

    // unpack accumulators
    float aW_lo, aW_hi, aT_lo, aT_hi, a0_lo, a0_hi;
    upk2(accW, aW_lo, aW_hi);
    upk2(accT, aT_lo, aT_hi);
    upk2(a0v,  a0_lo, a0_hi);
    float z0l, z0h, z1l, z1h, z2l, z2h;
    upk2(zp0, z0l, z0h); upk2(zp1, z1l, z1h); upk2(zp2, z2l, z2h);
    float lgz_lo = lg2f_(z0l) + lg2f_(z1l) + lg2f_(z2l);
    float lgz_hi = lg2f_(z0h) + lg2f_(z1h) + lg2f_(z2h);

    const float KADD = 38.0f - 19.0f * HALF_LN_2PI;

    // pixel lo
    float sumg_lo = fmaf(LN2F, lgp_lo, fmaf(-2.5f * LN2F, lgz_lo, -aW_lo - aT_lo)) + a0_lo + KADD;
    float psi0_lo, lg0_lo;
    psi_lg_s(a0_lo, psi0_lo, lg0_lo);
    float psia_lo = fmaf(LN2F, lg2f_(z_a0), -cs_a0);
    float kl_lo   = fmaf(-(a0_lo - 19.0f), psi0_lo, lg0_lo) + sumg_lo;
    float loss_lo = fmaf(0.01f, kl_lo, psi0_lo - psia_lo);
    if (ig0) loss_lo = 0.0f;

    // pixel hi
    float sumg_hi = fmaf(LN2F, lgp_hi, fmaf(-2.5f * LN2F, lgz_hi, -aW_hi - aT_hi)) + a0_hi + KADD;
    float psi0_hi, lg0_hi;
    psi_lg_s(a0_hi, psi0_hi, lg0_hi);
    float psia_hi = fmaf(LN2F, lg2f_(z_a1), -cs_a1);
    float kl_hi   = fmaf(-(a0_hi - 19.0f), psi0_hi, lg0_hi) + sumg_hi;
    float loss_hi = fmaf(0.01f, kl_hi, psi0_hi - psia_hi);
    if (ig1) loss_hi = 0.0f;

    float loss  = loss_lo + loss_hi;
    int   valid = (ig0 ? 0 : 1) + (ig1 ? 0 : 1);

    // warp reduction
#pragma unroll
    for (int o = 16; o; o >>= 1) {
        loss  += __shfl_down_sync(0xffffffffu, loss, o);
        valid += __shfl_down_sync(0xffffffffu, valid, o);
    }

    __shared__ float s_l[8];
    __shared__ int   s_v[8];
    int wid = threadIdx.x >> 5;
    int lid = threadIdx.x & 31;
    if (lid == 0) { s_l[wid] = loss; s_v[wid] = valid; }
    __syncthreads();

    if (threadIdx.x == 0) {
        float L = 0.0f;
        int   V = 0;
#pragma unroll
        for (int w = 0; w < 8; ++w) { L += s_l[w]; V += s_v[w]; }
        atomicAdd(&g_sum, (double)L);
        atomicAdd(&g_cnt, (unsigned long long)V);
    }
}

__global__ void bml_fin(float* out) {
    out[0] = (float)(g_sum / (double)g_cnt);
}

extern "C" void kernel_launch(void* const* d_in, const int* in_sizes, int n_in,
                              void* d_out, int out_size) {
    const float* pred = (const float*)d_in[0];
    const int*   tgt  = (const int*)d_in[1];
    float*       out  = (float*)d_out;

    bml_init<<<1, 1>>>();
    bml_main<<<NTHR_ / 256, 256>>>(pred, tgt);
    bml_fin<<<1, 1>>>(out);
}

// round 4
// speedup vs baseline: 1.1068x; 1.0360x over previous
#include <cuda_runtime.h>

// BeliefMatchingLoss: pred [8,19,512,512] f32, target [8,512,512] int32 -> scalar f32
// Single-kernel: compute + global reduce + finalize (last-block pattern, resets
// its own state so every graph replay is identical).
//
// loss_pix = 0.01*( lnG(a0) - (a0-19)*psi(a0) + sum_c g(a_c) ) + psi(a0) - psi(a_ans)
// g(x) expanded with shift-2 (z=x+2, P=x(x+1), S=Pp/P, Pp*z = 2P+3x+2):
//   g = lnP - 2.5*lnz - (x-1)*(c(z)+S) - t(z) + z - 0.5*ln(2pi)
// Logs batched: lnP in groups of 4 (one LG2 per pixel per group), lnz in
// groups of <=8. Reciprocals batched in groups of 4 via rcp of the product.
// All polynomial math packed 2 pixels/thread with fma.rn.f32x2.

typedef unsigned long long u64;

#define HW_   (512 * 512)
#define NC_   19
#define NPIX_ (8 * HW_)
#define NTHR_ (NPIX_ / 2)
#define NBLK_ (NTHR_ / 256)

#define LN2F        0.6931471805599453f
#define LOG2EF      1.4426950408889634f
#define HALF_LN_2PI 0.91893853320467274f

__device__ double             g_sum    = 0.0;
__device__ unsigned long long g_cnt    = 0ull;
__device__ unsigned int       g_arrive = 0u;

// ---- packed f32x2 helpers (u64 = {lo,hi} fp32 pair) ----
__device__ __forceinline__ u64 pk2(float a, float b) {
    u64 r; asm("mov.b64 %0,{%1,%2};" : "=l"(r) : "f"(a), "f"(b)); return r;
}
__device__ __forceinline__ void upk2(u64 v, float& a, float& b) {
    asm("mov.b64 {%0,%1},%2;" : "=f"(a), "=f"(b) : "l"(v));
}
__device__ __forceinline__ u64 f2fma(u64 a, u64 b, u64 c) {
    u64 d; asm("fma.rn.f32x2 %0,%1,%2,%3;" : "=l"(d) : "l"(a), "l"(b), "l"(c)); return d;
}
__device__ __forceinline__ u64 f2mul(u64 a, u64 b) {
    u64 d; asm("mul.rn.f32x2 %0,%1,%2;" : "=l"(d) : "l"(a), "l"(b)); return d;
}
__device__ __forceinline__ u64 f2add(u64 a, u64 b) {
    u64 d; asm("add.rn.f32x2 %0,%1,%2;" : "=l"(d) : "l"(a), "l"(b)); return d;
}
__device__ __forceinline__ float ex2f(float x) { float r; asm("ex2.approx.f32 %0,%1;" : "=f"(r) : "f"(x)); return r; }
__device__ __forceinline__ float lg2f_(float x){ float r; asm("lg2.approx.f32 %0,%1;" : "=f"(r) : "f"(x)); return r; }
__device__ __forceinline__ float rcpf_(float x){ float r; asm("rcp.approx.f32 %0,%1;" : "=f"(r) : "f"(x)); return r; }
__device__ __forceinline__ u64 rcp_2(u64 v) { float a, b; upk2(v, a, b); return pk2(rcpf_(a), rcpf_(b)); }

// scalar digamma+lgamma, shift-2 (used once per pixel, on a0 >> 1)
__device__ __forceinline__ void psi_lg_s(float x, float& psi, float& lg) {
    float z   = x + 2.0f;
    float P   = fmaf(x, x, x);
    float Pp  = fmaf(2.0f, x, 1.0f);
    float r   = rcpf_(P * z);
    float S   = Pp * (z * r);
    float rz  = P * r;
    float rz2 = rz * rz;
    float lnz = lg2f_(z) * LN2F;
    float lnP = lg2f_(P) * LN2F;
    float c = fmaf(rz, 0.5f, rz2 * fmaf(rz2, -1.0f / 120.0f, 1.0f / 12.0f));
    float t = rz * fmaf(rz2, -1.0f / 360.0f, 1.0f / 12.0f);
    psi = lnz - c - S;
    lg  = fmaf(z - 0.5f, lnz, -z) + HALF_LN_2PI + t - lnP;
}

struct ClsA { u64 x, z, P, Q; };

__global__ __launch_bounds__(256) void bml_main(const float* __restrict__ pred,
                                                const int*  __restrict__ tgt,
                                                float*      __restrict__ out) {
    int tix = blockIdx.x * 256 + threadIdx.x;
    int pix = tix * 2;
    int b   = pix >> 18;
    int hw  = pix & (HW_ - 1);
    const float* pp = pred + (size_t)b * NC_ * HW_ + hw;

    int2 tv  = *reinterpret_cast<const int2*>(tgt + pix);
    bool ig0 = (tv.x == 255), ig1 = (tv.y == 255);
    int  ta0 = ig0 ? 0 : tv.x;
    int  ta1 = ig1 ? 0 : tv.y;

    const u64 K1    = pk2(1.0f, 1.0f);
    const u64 K2    = pk2(2.0f, 2.0f);
    const u64 K3    = pk2(3.0f, 3.0f);
    const u64 KH    = pk2(0.5f, 0.5f);
    const u64 Km1   = pk2(-1.0f, -1.0f);
    const u64 K12   = pk2(1.0f / 12.0f, 1.0f / 12.0f);
    const u64 Km120 = pk2(-1.0f / 120.0f, -1.0f / 120.0f);
    const u64 Km360 = pk2(-1.0f / 360.0f, -1.0f / 360.0f);
    const u64 Z64   = pk2(0.0f, 0.0f);

    u64 accW = Z64, accT = Z64, a0v = Z64;
    u64 zp0 = K1, zp1 = K1, zp2 = K1;
    float lgp_lo = 0.0f, lgp_hi = 0.0f;
    float cs_a0 = 0.0f, cs_a1 = 0.0f, z_a0 = 1.0f, z_a1 = 1.0f;

#define STAGE1(s, c) do {                                                     \
        float2 pv = *reinterpret_cast<const float2*>(pp + (size_t)(c) * HW_); \
        (s).x = pk2(ex2f(pv.x * LOG2EF), ex2f(pv.y * LOG2EF));                \
        (s).z = f2add((s).x, K2);                                             \
        (s).P = f2fma((s).x, (s).x, (s).x);                                   \
        (s).Q = f2mul((s).P, (s).z);                                          \
    } while (0)

#define STAGE2(s, r, c, zpg) do {                                             \
        u64 rz  = f2mul((s).P, (r));                       /* 1/z */          \
        u64 S   = f2mul(f2fma(K2, (s).P, f2fma(K3, (s).x, K2)), (r));         \
        u64 rz2 = f2mul(rz, rz);                                              \
        u64 v_  = f2mul(rz2, f2fma(rz2, Km120, K12));                         \
        u64 cs  = f2add(f2fma(rz, KH, v_), S);                                \
        u64 tt  = f2mul(rz, f2fma(rz2, Km360, K12));                          \
        u64 xm1 = f2add((s).x, Km1);                                          \
        accW = f2fma(xm1, cs, accW);                                          \
        accT = f2add(accT, tt);                                               \
        a0v  = f2add(a0v, (s).x);                                             \
        (zpg) = f2mul((zpg), (s).z);                                          \
        float cslo, cshi, zlo, zhi;                                           \
        upk2(cs, cslo, cshi); upk2((s).z, zlo, zhi);                          \
        if ((c) == ta0) { cs_a0 = cslo; z_a0 = zlo; }                         \
        if ((c) == ta1) { cs_a1 = cshi; z_a1 = zhi; }                         \
    } while (0)

    // groups of 4 classes: one RCP (of Q-product) and one LG2 (of P-product) per pixel
#define GROUP4(c0, zpg) do {                                                  \
        ClsA s0, s1, s2, s3;                                                  \
        STAGE1(s0, (c0) + 0); STAGE1(s1, (c0) + 1);                           \
        STAGE1(s2, (c0) + 2); STAGE1(s3, (c0) + 3);                           \
        u64 Qab = f2mul(s0.Q, s1.Q);                                          \
        u64 Qcd = f2mul(s2.Q, s3.Q);                                          \
        u64 rr  = rcp_2(f2mul(Qab, Qcd));                                     \
        u64 rab = f2mul(rr, Qcd);                                             \
        u64 rcd = f2mul(rr, Qab);                                             \
        u64 r0 = f2mul(rab, s1.Q), r1 = f2mul(rab, s0.Q);                     \
        u64 r2 = f2mul(rcd, s3.Q), r3 = f2mul(rcd, s2.Q);                     \
        u64 Pg = f2mul(f2mul(s0.P, s1.P), f2mul(s2.P, s3.P));                 \
        float pgl, pgh; upk2(Pg, pgl, pgh);                                   \
        lgp_lo += lg2f_(pgl); lgp_hi += lg2f_(pgh);                           \
        STAGE2(s0, r0, (c0) + 0, zpg); STAGE2(s1, r1, (c0) + 1, zpg);         \
        STAGE2(s2, r2, (c0) + 2, zpg); STAGE2(s3, r3, (c0) + 3, zpg);         \
    } while (0)

    GROUP4(0,  zp0);
    GROUP4(4,  zp0);
    GROUP4(8,  zp1);
    GROUP4(12, zp1);
    { // tail group of 3 (classes 16,17,18)
        ClsA s0, s1, s2;
        STAGE1(s0, 16); STAGE1(s1, 17); STAGE1(s2, 18);
        u64 Qab = f2mul(s0.Q, s1.Q);
        u64 rr  = rcp_2(f2mul(Qab, s2.Q));
        u64 rab = f2mul(rr, s2.Q);
        u64 r2  = f2mul(rr, Qab);
        u64 r0 = f2mul(rab, s1.Q), r1 = f2mul(rab, s0.Q);
        u64 Pg = f2mul(f2mul(s0.P, s1.P), s2.P);
        float pgl, pgh; upk2(Pg, pgl, pgh);
        lgp_lo += lg2f_(pgl); lgp_hi += lg2f_(pgh);
        STAGE2(s0, r0, 16, zp2); STAGE2(s1, r1, 17, zp2); STAGE2(s2, r2, 18, zp2);
    }
#undef STAGE1
#undef STAGE2
#undef GROUP4

    float aW_lo, aW_hi, aT_lo, aT_hi, a0_lo, a0_hi;
    upk2(accW, aW_lo, aW_hi);
    upk2(accT, aT_lo, aT_hi);
    upk2(a0v,  a0_lo, a0_hi);
    float z0l, z0h, z1l, z1h, z2l, z2h;
    upk2(zp0, z0l, z0h); upk2(zp1, z1l, z1h); upk2(zp2, z2l, z2h);
    float lgz_lo = lg2f_(z0l) + lg2f_(z1l) + lg2f_(z2l);
    float lgz_hi = lg2f_(z0h) + lg2f_(z1h) + lg2f_(z2h);

    const float KADD = 38.0f - 19.0f * HALF_LN_2PI;

    float sumg_lo = fmaf(LN2F, lgp_lo, fmaf(-2.5f * LN2F, lgz_lo, -aW_lo - aT_lo)) + a0_lo + KADD;
    float psi0_lo, lg0_lo;
    psi_lg_s(a0_lo, psi0_lo, lg0_lo);
    float psia_lo = fmaf(LN2F, lg2f_(z_a0), -cs_a0);
    float kl_lo   = fmaf(-(a0_lo - 19.0f), psi0_lo, lg0_lo) + sumg_lo;
    float loss_lo = fmaf(0.01f, kl_lo, psi0_lo - psia_lo);
    if (ig0) loss_lo = 0.0f;

    float sumg_hi = fmaf(LN2F, lgp_hi, fmaf(-2.5f * LN2F, lgz_hi, -aW_hi - aT_hi)) + a0_hi + KADD;
    float psi0_hi, lg0_hi;
    psi_lg_s(a0_hi, psi0_hi, lg0_hi);
    float psia_hi = fmaf(LN2F, lg2f_(z_a1), -cs_a1);
    float kl_hi   = fmaf(-(a0_hi - 19.0f), psi0_hi, lg0_hi) + sumg_hi;
    float loss_hi = fmaf(0.01f, kl_hi, psi0_hi - psia_hi);
    if (ig1) loss_hi = 0.0f;

    float loss  = loss_lo + loss_hi;
    int   valid = (ig0 ? 0 : 1) + (ig1 ? 0 : 1);

#pragma unroll
    for (int o = 16; o; o >>= 1) {
        loss  += __shfl_down_sync(0xffffffffu, loss, o);
        valid += __shfl_down_sync(0xffffffffu, valid, o);
    }

    __shared__ float s_l[8];
    __shared__ int   s_v[8];
    int wid = threadIdx.x >> 5;
    int lid = threadIdx.x & 31;
    if (lid == 0) { s_l[wid] = loss; s_v[wid] = valid; }
    __syncthreads();

    if (threadIdx.x == 0) {
        float L = 0.0f;
        int   V = 0;
#pragma unroll
        for (int w = 0; w < 8; ++w) { L += s_l[w]; V += s_v[w]; }
        atomicAdd(&g_sum, (double)L);
        atomicAdd(&g_cnt, (unsigned long long)V);
        __threadfence();
        unsigned int n = atomicAdd(&g_arrive, 1u);
        if (n == (unsigned int)(NBLK_ - 1)) {
            __threadfence();
            double s = *((volatile double*)&g_sum);
            unsigned long long c = *((volatile unsigned long long*)&g_cnt);
            out[0] = (float)(s / (double)c);
            g_sum    = 0.0;
            g_cnt    = 0ull;
            g_arrive = 0u;
        }
    }
}

extern "C" void kernel_launch(void* const* d_in, const int* in_sizes, int n_in,
                              void* d_out, int out_size) {
    const float* pred = (const float*)d_in[0];
    const int*   tgt  = (const int*)d_in[1];
    float*       out  = (float*)d_out;

    bml_main<<<NBLK_, 256>>>(pred, tgt, out);
}